// round 2
// baseline (speedup 1.0000x reference)
#include <cuda_runtime.h>
#include <cuda_bf16.h>
#include <math.h>

#define TIMESTEPS 1000
#define BB 4
#define NN 2048
#define EE (NN * (NN - 1) / 2)   // 2096128

__device__ double g_sum;

__global__ void init_kernel() { g_sum = 0.0; }

__global__ __launch_bounds__(256) void diffusion_loss_kernel(
    const int* __restrict__ adj,
    const int* __restrict__ t,
    const float* __restrict__ u,
    const float* __restrict__ q)
{
    const int i = blockIdx.x;           // row index 0..N-1 (row i has i lower-tri elems)
    const int b = blockIdx.y;           // batch
    if (i == 0) return;

    const int tb = t[b];
    const float flip_e = 0.5f * (1.0f - powf(0.98f, (float)(tb + 1)));
    const int   tp     = (tb == 0) ? (TIMESTEPS - 1) : (tb - 1);   // JAX wraps Qt[-1] -> Qt[999]
    const float flip_p = 0.5f * (1.0f - powf(0.98f, (float)(tp + 1)));
    const float flip0  = 0.5f * (1.0f - 0.98f);
    const float one_m_fe = 1.0f - flip_e;
    const float one_m_fp = 1.0f - flip_p;
    const float one_m_f0 = 1.0f - flip0;

    const size_t rowoff = (size_t)b * NN * NN + (size_t)i * NN;
    const int*   arow = adj + rowoff;
    const float* urow = u + rowoff;
    const float* qrow = q + (size_t)b * EE + ((size_t)i * (i - 1)) / 2;

    float s = 0.0f;
    for (int j = threadIdx.x; j < i; j += blockDim.x) {
        const int   a  = arow[j];
        const float uu = urow[j];
        const float qa = qrow[j];

        const float p1 = a ? one_m_fe : flip_e;          // P(x=1 | adj)
        const int   x  = (uu < p1) ? 1 : 0;
        const float L1 = x ? one_m_f0 : flip0;           // Qt[0][x,1]
        const float P1 = a ? one_m_fp : flip_p;          // Qt[t-1][adj,1]
        const float Ev = (a == x) ? one_m_fe : flip_e;   // Qt[t][adj,x]
        const float qt = L1 * P1 / Ev;

        s += fmaxf(qa, 0.0f) - qa * qt + log1pf(expf(-fabsf(qa)));
    }

    // block reduction: warp shuffles then shared
    for (int off = 16; off > 0; off >>= 1)
        s += __shfl_down_sync(0xFFFFFFFFu, s, off);

    __shared__ float warp_sums[8];
    const int lane = threadIdx.x & 31;
    const int wid  = threadIdx.x >> 5;
    if (lane == 0) warp_sums[wid] = s;
    __syncthreads();
    if (wid == 0) {
        float v = (lane < (blockDim.x >> 5)) ? warp_sums[lane] : 0.0f;
        for (int off = 4; off > 0; off >>= 1)
            v += __shfl_down_sync(0xFFFFFFFFu, v, off);
        if (lane == 0)
            atomicAdd(&g_sum, (double)v);
    }
}

__global__ void finish_kernel(float* out)
{
    out[0] = (float)(g_sum / (double)((size_t)BB * EE));
}

extern "C" void kernel_launch(void* const* d_in, const int* in_sizes, int n_in,
                              void* d_out, int out_size)
{
    const int*   adj = (const int*)d_in[0];    // (B,N,N) int32
    const int*   t   = (const int*)d_in[1];    // (B,)    int32
    const float* u   = (const float*)d_in[2];  // (B,N,N) float32
    const float* q   = (const float*)d_in[3];  // (B,E)   float32
    float* out = (float*)d_out;

    init_kernel<<<1, 1>>>();
    dim3 grid(NN, BB);
    diffusion_loss_kernel<<<grid, 256>>>(adj, t, u, q);
    finish_kernel<<<1, 1>>>(out);
}